// round 2
// baseline (speedup 1.0000x reference)
#include <cuda_runtime.h>

#define D 512
#define D4 (D / 4)
#define EPS 1e-9f

// Accumulators: [0]=sum_e, [1]=sum_e2, [2]=sum_t, [3]=sum_t2, [4]=sum_et
// Zero-initialized at module load. finalize_kernel re-zeroes after use, so
// the invariant "g_acc == 0 at entry of kernel_launch" holds across the
// correctness run and every graph replay (deterministic).
__device__ float g_acc[5 * D];

__global__ void __launch_bounds__(128) stats_kernel(
        const float4* __restrict__ e,
        const float4* __restrict__ t,
        int rows_per_block) {
    const int c4 = threadIdx.x;                       // 0..127: group of 4 columns
    const long long r0 = (long long)blockIdx.x * rows_per_block;

    // 5 stats x 4 columns, register-resident
    float se[4]  = {0.f, 0.f, 0.f, 0.f};
    float se2[4] = {0.f, 0.f, 0.f, 0.f};
    float st[4]  = {0.f, 0.f, 0.f, 0.f};
    float st2[4] = {0.f, 0.f, 0.f, 0.f};
    float set[4] = {0.f, 0.f, 0.f, 0.f};

    const float4* ep = e + r0 * D4 + c4;
    const float4* tp = t + r0 * D4 + c4;

    #pragma unroll 4
    for (int r = 0; r < rows_per_block; ++r) {
        float4 ev = ep[(long long)r * D4];
        float4 tv = tp[(long long)r * D4];
        float evs[4] = {ev.x, ev.y, ev.z, ev.w};
        float tvs[4] = {tv.x, tv.y, tv.z, tv.w};
        #pragma unroll
        for (int k = 0; k < 4; ++k) {
            se[k]  += evs[k];
            se2[k] += evs[k] * evs[k];
            st[k]  += tvs[k];
            st2[k] += tvs[k] * tvs[k];
            set[k] += evs[k] * tvs[k];
        }
    }

    const int col = c4 * 4;
    #pragma unroll
    for (int k = 0; k < 4; ++k) {
        atomicAdd(&g_acc[0 * D + col + k], se[k]);
        atomicAdd(&g_acc[1 * D + col + k], se2[k]);
        atomicAdd(&g_acc[2 * D + col + k], st[k]);
        atomicAdd(&g_acc[3 * D + col + k], st2[k]);
        atomicAdd(&g_acc[4 * D + col + k], set[k]);
    }
}

__global__ void finalize_kernel(float* __restrict__ out, float B) {
    const int col = threadIdx.x;   // 512 threads, 1 block
    __shared__ float red[512];

    float se  = g_acc[0 * D + col];
    float se2 = g_acc[1 * D + col];
    float st  = g_acc[2 * D + col];
    float st2 = g_acc[3 * D + col];
    float set = g_acc[4 * D + col];

    // Re-zero for the next graph replay (each thread owns its 5 entries).
    g_acc[0 * D + col] = 0.f;
    g_acc[1 * D + col] = 0.f;
    g_acc[2 * D + col] = 0.f;
    g_acc[3 * D + col] = 0.f;
    g_acc[4 * D + col] = 0.f;

    float me = se / B;
    float mt = st / B;
    // unbiased variance (ddof=1)
    float var_e = (se2 - B * me * me) / (B - 1.0f);
    float var_t = (st2 - B * mt * mt) / (B - 1.0f);
    float sd_e = sqrtf(fmaxf(var_e, 0.0f)) + EPS;
    float sd_t = sqrtf(fmaxf(var_t, 0.0f)) + EPS;

    // sum_b (e-me)(t-mt) = set - B*me*mt
    float cov = set - B * me * mt;
    float c = cov / (sd_e * sd_t) / B;
    float d = 1.0f - c;
    float partial = d * d;

    red[col] = partial;
    __syncthreads();
    #pragma unroll
    for (int s = 256; s > 0; s >>= 1) {
        if (col < s) red[col] += red[col + s];
        __syncthreads();
    }
    if (col == 0) out[0] = red[0];
}

extern "C" void kernel_launch(void* const* d_in, const int* in_sizes, int n_in,
                              void* d_out, int out_size) {
    const float* e = (const float*)d_in[0];
    const float* t = (const float*)d_in[1];
    float* out = (float*)d_out;

    const long long total = in_sizes[0];
    const int B = (int)(total / D);          // 65536

    const int nblocks = 1024;                // 64 rows per block
    const int rows_per_block = B / nblocks;

    stats_kernel<<<nblocks, 128>>>((const float4*)e, (const float4*)t, rows_per_block);
    finalize_kernel<<<1, D>>>(out, (float)B);
}

// round 3
// speedup vs baseline: 1.6356x; 1.6356x over previous
#include <cuda_runtime.h>

#define D 512
#define EPS 1e-9f
#define NBLOCKS 512

// Accumulators: [0]=sum_e, [1]=sum_e2, [2]=sum_t, [3]=sum_t2, [4]=sum_et
// Zero-initialized at module load; the last block re-zeroes after consuming,
// so "g_acc == 0, g_ticket == 0 at kernel entry" holds on every graph replay.
__device__ float g_acc[5 * D];
__device__ unsigned int g_ticket;

__global__ void __launch_bounds__(D) stats_finalize_kernel(
        const float* __restrict__ e,
        const float* __restrict__ t,
        int rows_per_block,
        float* __restrict__ out,
        float B) {
    const int col = threadIdx.x;                 // 512 threads = 512 columns
    const long long r0 = (long long)blockIdx.x * rows_per_block;

    float se = 0.f, se2 = 0.f, st = 0.f, st2 = 0.f, set = 0.f;

    const float* ep = e + r0 * D + col;
    const float* tp = t + r0 * D + col;

    #pragma unroll 4
    for (int r = 0; r < rows_per_block; ++r) {
        float ev = ep[(long long)r * D];
        float tv = tp[(long long)r * D];
        se  += ev;
        se2 += ev * ev;
        st  += tv;
        st2 += tv * tv;
        set += ev * tv;
    }

    atomicAdd(&g_acc[0 * D + col], se);
    atomicAdd(&g_acc[1 * D + col], se2);
    atomicAdd(&g_acc[2 * D + col], st);
    atomicAdd(&g_acc[3 * D + col], st2);
    atomicAdd(&g_acc[4 * D + col], set);

    // ---- last-block-done finalize ----
    __threadfence();                 // order this thread's atomics before ticket
    __syncthreads();                 // all threads' atomics issued + fenced

    __shared__ bool is_last;
    if (col == 0) {
        unsigned int t_ = atomicAdd(&g_ticket, 1u);
        is_last = (t_ == (unsigned int)(gridDim.x - 1));
    }
    __syncthreads();
    if (!is_last) return;

    // Last block: all prior blocks' atomics are visible at L2. Read with .cg
    // (atomics bypass L1, so avoid any stale L1 lines).
    float fse  = __ldcg(&g_acc[0 * D + col]);
    float fse2 = __ldcg(&g_acc[1 * D + col]);
    float fst  = __ldcg(&g_acc[2 * D + col]);
    float fst2 = __ldcg(&g_acc[3 * D + col]);
    float fset = __ldcg(&g_acc[4 * D + col]);

    // Re-zero for the next graph replay.
    g_acc[0 * D + col] = 0.f;
    g_acc[1 * D + col] = 0.f;
    g_acc[2 * D + col] = 0.f;
    g_acc[3 * D + col] = 0.f;
    g_acc[4 * D + col] = 0.f;
    if (col == 0) g_ticket = 0u;

    float me = fse / B;
    float mt = fst / B;
    // unbiased variance (ddof=1)
    float var_e = (fse2 - B * me * me) / (B - 1.0f);
    float var_t = (fst2 - B * mt * mt) / (B - 1.0f);
    float sd_e = sqrtf(fmaxf(var_e, 0.0f)) + EPS;
    float sd_t = sqrtf(fmaxf(var_t, 0.0f)) + EPS;

    // sum_b (e-me)(t-mt) = set - B*me*mt
    float cov = fset - B * me * mt;
    float c = cov / (sd_e * sd_t) / B;
    float d = 1.0f - c;
    float partial = d * d;

    __shared__ float red[D];
    red[col] = partial;
    __syncthreads();
    #pragma unroll
    for (int s = 256; s > 0; s >>= 1) {
        if (col < s) red[col] += red[col + s];
        __syncthreads();
    }
    if (col == 0) out[0] = red[0];
}

extern "C" void kernel_launch(void* const* d_in, const int* in_sizes, int n_in,
                              void* d_out, int out_size) {
    const float* e = (const float*)d_in[0];
    const float* t = (const float*)d_in[1];
    float* out = (float*)d_out;

    const long long total = in_sizes[0];
    const int B = (int)(total / D);          // 65536
    const int rows_per_block = B / NBLOCKS;  // 128

    stats_finalize_kernel<<<NBLOCKS, D>>>(e, t, rows_per_block, out, (float)B);
}